// round 8
// baseline (speedup 1.0000x reference)
#include <cuda_runtime.h>
#include <cuda_bf16.h>
#include <math.h>
#include <stdint.h>

#define D 256
#define N_TGT 40000
#define NNZ_MAX 300000
#define N_TGT_PAD 40960          // 40 scan blocks x 1024
#define BM 64
#define NBLK (N_TGT / BM)        // 625
#define KC 32
#define NCHUNK (D / KC)          // 8

// ---------------- device scratch (no-alloc rule: __device__ globals) -------
__device__ float g_mapped[(size_t)N_TGT * D];
__device__ __nv_bfloat16 g_wt_hi[D * D];
__device__ __nv_bfloat16 g_wt_lo[D * D];
__device__ int   g_row_cnt[N_TGT_PAD];   // per-row edge count
__device__ int   g_loc[N_TGT_PAD];       // block-local exclusive scan / cursor
__device__ int   g_blk[40];              // per-scan-block totals
__device__ int   g_blk_off[40];          // exclusive scan of totals
__device__ int   g_csr_col[NNZ_MAX];
__device__ float g_csr_val[NNZ_MAX];

// ---------------- GEMM smem layout (unchanged from R3, it works) -----------
#define SOFF_AHI 0
#define SOFF_ALO 5120
#define SOFF_BHI 10240
#define SOFF_BLO 30720
#define SOFF_H 0
#define H_STRIDE 260
#define SOFF_BIAS 66560
#define SOFF_GAMMA 67584
#define SOFF_BETA 68608
#define SMEM_TOTAL 69632

__device__ __forceinline__ void split2(float f0, float f1,
                                       uint32_t& hi, uint32_t& lo) {
    __nv_bfloat16 h0 = __float2bfloat16(f0);
    __nv_bfloat16 h1 = __float2bfloat16(f1);
    __nv_bfloat16 l0 = __float2bfloat16(f0 - __bfloat162float(h0));
    __nv_bfloat16 l1 = __float2bfloat16(f1 - __bfloat162float(h1));
    __nv_bfloat162 hp(h0, h1), lp(l0, l1);
    hi = *(uint32_t*)&hp;
    lo = *(uint32_t*)&lp;
}

__device__ __forceinline__ void mma_bf16(float* c, const uint32_t* a,
                                         uint32_t b0, uint32_t b1) {
    asm volatile(
        "mma.sync.aligned.m16n8k16.row.col.f32.bf16.bf16.f32 "
        "{%0,%1,%2,%3}, {%4,%5,%6,%7}, {%8,%9}, {%0,%1,%2,%3};"
        : "+f"(c[0]), "+f"(c[1]), "+f"(c[2]), "+f"(c[3])
        : "r"(a[0]), "r"(a[1]), "r"(a[2]), "r"(a[3]), "r"(b0), "r"(b1));
}

// ---------------------------------------------------------------------------
// CSR build kernels
// ---------------------------------------------------------------------------
__global__ void hist_kernel(const int* __restrict__ rows, int nnz) {
    int e = blockIdx.x * 256 + threadIdx.x;
    if (e < nnz) atomicAdd(&g_row_cnt[__ldg(rows + e)], 1);
}

// Block-local exclusive scan: 40 blocks x 1024 ints each.
__global__ __launch_bounds__(256) void scanA_kernel() {
    __shared__ int swarp[8];
    const int b = blockIdx.x, tid = threadIdx.x;
    const int lane = tid & 31, wid = tid >> 5;
    int4 v = ((const int4*)g_row_cnt)[b * 256 + tid];
    int tsum = v.x + v.y + v.z + v.w;
    int inc = tsum;
#pragma unroll
    for (int o = 1; o < 32; o <<= 1) {
        int n = __shfl_up_sync(0xffffffffu, inc, o);
        if (lane >= o) inc += n;
    }
    if (lane == 31) swarp[wid] = inc;
    __syncthreads();
    if (wid == 0 && lane < 8) {
        int s = swarp[lane];
        int si = s;
#pragma unroll
        for (int o = 1; o < 8; o <<= 1) {
            int n = __shfl_up_sync(0xffu, si, o);
            if (lane >= o) si += n;
        }
        swarp[lane] = si - s;               // exclusive warp offset
        if (lane == 7) g_blk[b] = si;       // block total
    }
    __syncthreads();
    int base = swarp[wid] + inc - tsum;
    int4 o4;
    o4.x = base;
    o4.y = base + v.x;
    o4.z = o4.y + v.y;
    o4.w = o4.z + v.z;
    ((int4*)g_loc)[b * 256 + tid] = o4;
}

// Exclusive scan of the 40 block totals (1 warp).
__global__ void scanB_kernel() {
    int l = threadIdx.x;
    int s0 = (2 * l < 40) ? g_blk[2 * l] : 0;
    int s1 = (2 * l + 1 < 40) ? g_blk[2 * l + 1] : 0;
    int p = s0 + s1, inc = p;
#pragma unroll
    for (int o = 1; o < 32; o <<= 1) {
        int n = __shfl_up_sync(0xffffffffu, inc, o);
        if (l >= o) inc += n;
    }
    int excl = inc - p;
    if (2 * l < 40) g_blk_off[2 * l] = excl;
    if (2 * l + 1 < 40) g_blk_off[2 * l + 1] = excl + s0;
}

// Bucket edges into CSR order.  g_loc doubles as the cursor: after this
// kernel g_loc[r] = local_excl[r] + cnt[r].
__global__ void bucket_kernel(const int* __restrict__ rows,
                              const int* __restrict__ cols,
                              const float* __restrict__ vals, int nnz) {
    int e = blockIdx.x * 256 + threadIdx.x;
    if (e >= nnz) return;
    int r = __ldg(rows + e);
    int lp = atomicAdd(&g_loc[r], 1);
    int pos = lp + g_blk_off[r >> 10];
    g_csr_col[pos] = __ldg(cols + e);
    g_csr_val[pos] = __ldg(vals + e);
}

// ---------------------------------------------------------------------------
// Gather SpMM: one warp per target row, register accumulation, single store.
// ---------------------------------------------------------------------------
__global__ __launch_bounds__(256) void spmm_gather_kernel(
        const float* __restrict__ x) {
    const int wid = threadIdx.x >> 5;
    const int lane = threadIdx.x & 31;
    const int r = blockIdx.x * 8 + wid;          // grid = 5000 -> r < 40000

    const int cnt = g_row_cnt[r];
    const int start = g_loc[r] + g_blk_off[r >> 10] - cnt;

    float4 a0 = make_float4(0.f, 0.f, 0.f, 0.f);
    float4 a1 = make_float4(0.f, 0.f, 0.f, 0.f);

    for (int j = 0; j < cnt; ++j) {
        int c = __ldg(&g_csr_col[start + j]);
        float v = __ldg(&g_csr_val[start + j]);
        const float4* xs = (const float4*)(x + (size_t)c * D);
        float4 x0 = __ldg(xs + lane);
        float4 x1 = __ldg(xs + lane + 32);
        a0.x += v * x0.x; a0.y += v * x0.y; a0.z += v * x0.z; a0.w += v * x0.w;
        a1.x += v * x1.x; a1.y += v * x1.y; a1.z += v * x1.z; a1.w += v * x1.w;
    }
    float4* mr = (float4*)(g_mapped + (size_t)r * D);
    mr[lane] = a0;
    mr[lane + 32] = a1;
}

// ---------------------------------------------------------------------------
// W transpose + bf16 split: 64 blocks, 32x32 tiles, coalesced both ways.
// ---------------------------------------------------------------------------
__global__ __launch_bounds__(256) void wconv_kernel(const float* __restrict__ W) {
    __shared__ float t[32][33];
    const int tid = threadIdx.x;
    const int k0 = (blockIdx.x >> 3) * 32;
    const int n0 = (blockIdx.x & 7) * 32;
    {
        int row = tid >> 3, c4 = tid & 7;
        float4 v = __ldg((const float4*)(W + (size_t)(k0 + row) * D + n0 + c4 * 4));
        t[row][c4 * 4 + 0] = v.x;
        t[row][c4 * 4 + 1] = v.y;
        t[row][c4 * 4 + 2] = v.z;
        t[row][c4 * 4 + 3] = v.w;
    }
    __syncthreads();
    {
        int nl = tid >> 3, kq = (tid & 7) * 4;
        uint16_t h[4], l[4];
#pragma unroll
        for (int i = 0; i < 4; ++i) {
            float v = t[kq + i][nl];
            __nv_bfloat16 hb = __float2bfloat16(v);
            __nv_bfloat16 lb = __float2bfloat16(v - __bfloat162float(hb));
            h[i] = *(uint16_t*)&hb;
            l[i] = *(uint16_t*)&lb;
        }
        size_t o = (size_t)(n0 + nl) * D + k0 + kq;
        *(uint2*)(g_wt_hi + o) = *(uint2*)h;
        *(uint2*)(g_wt_lo + o) = *(uint2*)l;
    }
}

// ---------------------------------------------------------------------------
// GEMM + bias + LayerNorm + GELU (identical to the R3 passing version).
// ---------------------------------------------------------------------------
extern __shared__ char dynsmem[];

__global__ __launch_bounds__(256, 2) void gemm_ln_gelu_kernel(
        const float* __restrict__ bias,
        const float* __restrict__ gamma,
        const float* __restrict__ beta,
        float* __restrict__ out) {
    char* sm = dynsmem;
    const int tid = threadIdx.x;
    const int wid = tid >> 5;
    const int lane = tid & 31;
    const int gr = lane >> 2;
    const int tc = lane & 3;
    const int warp_m = wid & 1;
    const int warp_n = wid >> 1;
    const int row0 = blockIdx.x * BM;

    {
        float* sB = (float*)(sm + SOFF_BIAS);
        float* sG = (float*)(sm + SOFF_GAMMA);
        float* sBe = (float*)(sm + SOFF_BETA);
        sB[tid] = bias[tid];
        sG[tid] = gamma[tid];
        sBe[tid] = beta[tid];
    }

    float acc[2][8][4];
#pragma unroll
    for (int mt = 0; mt < 2; ++mt)
#pragma unroll
        for (int nt = 0; nt < 8; ++nt)
#pragma unroll
            for (int q = 0; q < 4; ++q) acc[mt][nt][q] = 0.f;

    const uint16_t* pAhi = (const uint16_t*)(sm + SOFF_AHI);
    const uint16_t* pAlo = (const uint16_t*)(sm + SOFF_ALO);
    const uint16_t* pBhi = (const uint16_t*)(sm + SOFF_BHI);
    const uint16_t* pBlo = (const uint16_t*)(sm + SOFF_BLO);

#pragma unroll 1
    for (int kc = 0; kc < NCHUNK; ++kc) {
        __syncthreads();
        {
            int r = tid >> 2, seg = tid & 3;
            const float4* ap = (const float4*)(g_mapped +
                                (size_t)(row0 + r) * D + kc * KC + seg * 8);
            float4 a0 = __ldg(ap), a1 = __ldg(ap + 1);
            uint32_t h[4], l[4];
            split2(a0.x, a0.y, h[0], l[0]);
            split2(a0.z, a0.w, h[1], l[1]);
            split2(a1.x, a1.y, h[2], l[2]);
            split2(a1.z, a1.w, h[3], l[3]);
            uint32_t off = (uint32_t)(r * 80 + seg * 16);
            *(uint4*)(sm + SOFF_AHI + off) = make_uint4(h[0], h[1], h[2], h[3]);
            *(uint4*)(sm + SOFF_ALO + off) = make_uint4(l[0], l[1], l[2], l[3]);
        }
#pragma unroll
        for (int i = 0; i < 4; ++i) {
            int task = i * 256 + tid;
            int n = task >> 2, seg = task & 3;
            size_t gsrc = (size_t)n * D + kc * KC + seg * 8;
            uint32_t off = (uint32_t)(n * 80 + seg * 16);
            *(uint4*)(sm + SOFF_BHI + off) = *(const uint4*)(g_wt_hi + gsrc);
            *(uint4*)(sm + SOFF_BLO + off) = *(const uint4*)(g_wt_lo + gsrc);
        }
        __syncthreads();

#pragma unroll
        for (int ks = 0; ks < 2; ++ks) {
            uint32_t ahi[2][4], alo[2][4];
#pragma unroll
            for (int mt = 0; mt < 2; ++mt) {
                int ar = warp_m * 32 + mt * 16 + gr;
                int ak = ks * 16 + tc * 2;
                const uint16_t* ph = pAhi + ar * 40 + ak;
                const uint16_t* pl = pAlo + ar * 40 + ak;
                ahi[mt][0] = *(const uint32_t*)(ph);
                ahi[mt][1] = *(const uint32_t*)(ph + 320);
                ahi[mt][2] = *(const uint32_t*)(ph + 8);
                ahi[mt][3] = *(const uint32_t*)(ph + 328);
                alo[mt][0] = *(const uint32_t*)(pl);
                alo[mt][1] = *(const uint32_t*)(pl + 320);
                alo[mt][2] = *(const uint32_t*)(pl + 8);
                alo[mt][3] = *(const uint32_t*)(pl + 328);
            }
#pragma unroll
            for (int nt = 0; nt < 8; ++nt) {
                int bn = warp_n * 64 + nt * 8 + gr;
                int bk = ks * 16 + tc * 2;
                uint32_t bh0 = *(const uint32_t*)(pBhi + bn * 40 + bk);
                uint32_t bh1 = *(const uint32_t*)(pBhi + bn * 40 + bk + 8);
                uint32_t bl0 = *(const uint32_t*)(pBlo + bn * 40 + bk);
                uint32_t bl1 = *(const uint32_t*)(pBlo + bn * 40 + bk + 8);
#pragma unroll
                for (int mt = 0; mt < 2; ++mt) {
                    mma_bf16(acc[mt][nt], ahi[mt], bh0, bh1);
                    mma_bf16(acc[mt][nt], ahi[mt], bl0, bl1);
                    mma_bf16(acc[mt][nt], alo[mt], bh0, bh1);
                }
            }
        }
    }
    __syncthreads();

    {
        float* sH = (float*)(sm + SOFF_H);
        const float* sB = (const float*)(sm + SOFF_BIAS);
#pragma unroll
        for (int mt = 0; mt < 2; ++mt) {
#pragma unroll
            for (int nt = 0; nt < 8; ++nt) {
                int r = warp_m * 32 + mt * 16 + gr;
                int c = warp_n * 64 + nt * 8 + tc * 2;
                float b0 = sB[c], b1 = sB[c + 1];
                float* p0 = &sH[r * H_STRIDE + c];
                p0[0] = acc[mt][nt][0] + b0;
                p0[1] = acc[mt][nt][1] + b1;
                float* p1 = &sH[(r + 8) * H_STRIDE + c];
                p1[0] = acc[mt][nt][2] + b0;
                p1[1] = acc[mt][nt][3] + b1;
            }
        }
    }
    __syncthreads();

    {
        const float* sH = (const float*)(sm + SOFF_H);
        const float* sG = (const float*)(sm + SOFF_GAMMA);
        const float* sBe = (const float*)(sm + SOFF_BETA);
#pragma unroll
        for (int rr = 0; rr < 8; ++rr) {
            const int r = wid * 8 + rr;
            float v[8];
            float s = 0.f;
#pragma unroll
            for (int j = 0; j < 8; ++j) {
                v[j] = sH[r * H_STRIDE + lane + j * 32];
                s += v[j];
            }
#pragma unroll
            for (int o = 16; o; o >>= 1) s += __shfl_xor_sync(0xffffffffu, s, o);
            const float mu = s * (1.f / 256.f);
            float q = 0.f;
#pragma unroll
            for (int j = 0; j < 8; ++j) {
                float d = v[j] - mu;
                q += d * d;
            }
#pragma unroll
            for (int o = 16; o; o >>= 1) q += __shfl_xor_sync(0xffffffffu, q, o);
            const float rstd = rsqrtf(q * (1.f / 256.f) + 1e-5f);

            float* orow = out + (size_t)(row0 + r) * D;
#pragma unroll
            for (int j = 0; j < 8; ++j) {
                const int c = lane + j * 32;
                float t = (v[j] - mu) * rstd * sG[c] + sBe[c];
                orow[c] = 0.5f * t * (1.f + erff(t * 0.70710678118654752f));
            }
        }
    }
}

// ---------------------------------------------------------------------------
// Launch.  Inputs: x, rows, cols, vals, W, b, gamma, beta, num_targets.
// Order chosen so ncu's "-s 5" capture lands on spmm_gather_kernel.
// ---------------------------------------------------------------------------
extern "C" void kernel_launch(void* const* d_in, const int* in_sizes, int n_in,
                              void* d_out, int out_size) {
    const float* x     = (const float*)d_in[0];
    const int*   rows  = (const int*)d_in[1];
    const int*   cols  = (const int*)d_in[2];
    const float* vals  = (const float*)d_in[3];
    const float* W     = (const float*)d_in[4];
    const float* bias  = (const float*)d_in[5];
    const float* gamma = (const float*)d_in[6];
    const float* beta  = (const float*)d_in[7];

    const int nnz = in_sizes[1];
    const int eblk = (nnz + 255) / 256;

    // 0) zero per-row counters (160 KB)
    void* cnt_ptr = nullptr;
    cudaGetSymbolAddress(&cnt_ptr, g_row_cnt);
    cudaMemsetAsync(cnt_ptr, 0, N_TGT_PAD * sizeof(int));

    // 1-4) CSR build
    hist_kernel<<<eblk, 256>>>(rows, nnz);
    scanA_kernel<<<40, 256>>>();
    scanB_kernel<<<1, 32>>>();
    bucket_kernel<<<eblk, 256>>>(rows, cols, vals, nnz);

    // 5) gather SpMM (no atomics, no memset of mapped)
    spmm_gather_kernel<<<N_TGT / 8, 256>>>(x);

    // 6) W transpose + bf16 split
    wconv_kernel<<<64, 256>>>(W);

    // 7) tensor-core GEMM + bias + LN + GELU
    cudaFuncSetAttribute(gemm_ln_gelu_kernel,
                         cudaFuncAttributeMaxDynamicSharedMemorySize,
                         SMEM_TOTAL);
    gemm_ln_gelu_kernel<<<NBLK, 256, SMEM_TOTAL>>>(
        bias, gamma, beta, (float*)d_out);
}

// round 9
// speedup vs baseline: 1.0352x; 1.0352x over previous
#include <cuda_runtime.h>
#include <cuda_bf16.h>
#include <math.h>
#include <stdint.h>

#define D 256
#define N_TGT 40000
#define NNZ_MAX 300000
#define N_TGT_PAD 40960          // 40 scan blocks x 1024
#define BM 64
#define NBLK (N_TGT / BM)        // 625
#define KC 32
#define NCHUNK (D / KC)          // 8

// ---------------- device scratch ----------------
__device__ __nv_bfloat16 g_mapped_hi[(size_t)N_TGT * D];
__device__ __nv_bfloat16 g_mapped_lo[(size_t)N_TGT * D];
__device__ __nv_bfloat16 g_wt_hi[D * D];
__device__ __nv_bfloat16 g_wt_lo[D * D];
__device__ int   g_row_cnt[N_TGT_PAD];
__device__ int   g_loc[N_TGT_PAD];
__device__ int   g_blk[40];
__device__ int   g_blk_off[40];
__device__ int2  g_csr_pack[NNZ_MAX];     // (col, val bits)

// ---------------- GEMM smem: double-buffered staging ----------------
// per buffer: Ahi 64x80B=5120, Alo 5120, Bhi 256x80B=20480, Blo 20480
#define OFF_AHI 0
#define OFF_ALO 5120
#define OFF_BHI 10240
#define OFF_BLO 30720
#define BUF_STRIDE 51200
// h tile (phase 2) overlaps the buffers
#define SOFF_H 0
#define H_STRIDE 260
#define SOFF_BIAS  102400
#define SOFF_GAMMA 103424
#define SOFF_BETA  104448
#define SMEM_TOTAL 105472

__device__ __forceinline__ uint32_t smem_u32(const void* p) {
    uint32_t a;
    asm("{ .reg .u64 t; cvta.to.shared.u64 t, %1; cvt.u32.u64 %0, t; }"
        : "=r"(a) : "l"(p));
    return a;
}

__device__ __forceinline__ void cpasync16(uint32_t dst, const void* src) {
    asm volatile("cp.async.ca.shared.global [%0], [%1], 16;"
                 :: "r"(dst), "l"(src) : "memory");
}

__device__ __forceinline__ void split2(float f0, float f1,
                                       uint32_t& hi, uint32_t& lo) {
    __nv_bfloat16 h0 = __float2bfloat16(f0);
    __nv_bfloat16 h1 = __float2bfloat16(f1);
    __nv_bfloat16 l0 = __float2bfloat16(f0 - __bfloat162float(h0));
    __nv_bfloat16 l1 = __float2bfloat16(f1 - __bfloat162float(h1));
    __nv_bfloat162 hp(h0, h1), lp(l0, l1);
    hi = *(uint32_t*)&hp;
    lo = *(uint32_t*)&lp;
}

__device__ __forceinline__ void mma_bf16(float* c, const uint32_t* a,
                                         uint32_t b0, uint32_t b1) {
    asm volatile(
        "mma.sync.aligned.m16n8k16.row.col.f32.bf16.bf16.f32 "
        "{%0,%1,%2,%3}, {%4,%5,%6,%7}, {%8,%9}, {%0,%1,%2,%3};"
        : "+f"(c[0]), "+f"(c[1]), "+f"(c[2]), "+f"(c[3])
        : "r"(a[0]), "r"(a[1]), "r"(a[2]), "r"(a[3]), "r"(b0), "r"(b1));
}

// ---------------------------------------------------------------------------
// CSR build
// ---------------------------------------------------------------------------
__global__ void hist_kernel(const int* __restrict__ rows, int nnz) {
    int e = blockIdx.x * 256 + threadIdx.x;
    if (e < nnz) atomicAdd(&g_row_cnt[__ldg(rows + e)], 1);
}

__global__ __launch_bounds__(256) void scanA_kernel() {
    __shared__ int swarp[8];
    const int b = blockIdx.x, tid = threadIdx.x;
    const int lane = tid & 31, wid = tid >> 5;
    int4 v = ((const int4*)g_row_cnt)[b * 256 + tid];
    int tsum = v.x + v.y + v.z + v.w;
    int inc = tsum;
#pragma unroll
    for (int o = 1; o < 32; o <<= 1) {
        int n = __shfl_up_sync(0xffffffffu, inc, o);
        if (lane >= o) inc += n;
    }
    if (lane == 31) swarp[wid] = inc;
    __syncthreads();
    if (wid == 0 && lane < 8) {
        int s = swarp[lane];
        int si = s;
#pragma unroll
        for (int o = 1; o < 8; o <<= 1) {
            int n = __shfl_up_sync(0xffu, si, o);
            if (lane >= o) si += n;
        }
        swarp[lane] = si - s;
        if (lane == 7) g_blk[b] = si;
    }
    __syncthreads();
    int base = swarp[wid] + inc - tsum;
    int4 o4;
    o4.x = base;
    o4.y = base + v.x;
    o4.z = o4.y + v.y;
    o4.w = o4.z + v.z;
    ((int4*)g_loc)[b * 256 + tid] = o4;
}

__global__ void scanB_kernel() {
    int l = threadIdx.x;
    int s0 = (2 * l < 40) ? g_blk[2 * l] : 0;
    int s1 = (2 * l + 1 < 40) ? g_blk[2 * l + 1] : 0;
    int p = s0 + s1, inc = p;
#pragma unroll
    for (int o = 1; o < 32; o <<= 1) {
        int n = __shfl_up_sync(0xffffffffu, inc, o);
        if (l >= o) inc += n;
    }
    int excl = inc - p;
    if (2 * l < 40) g_blk_off[2 * l] = excl;
    if (2 * l + 1 < 40) g_blk_off[2 * l + 1] = excl + s0;
}

__global__ void bucket_kernel(const int* __restrict__ rows,
                              const int* __restrict__ cols,
                              const float* __restrict__ vals, int nnz) {
    int e = blockIdx.x * 256 + threadIdx.x;
    if (e >= nnz) return;
    int r = __ldg(rows + e);
    int lp = atomicAdd(&g_loc[r], 1);
    int pos = lp + g_blk_off[r >> 10];
    g_csr_pack[pos] = make_int2(__ldg(cols + e),
                                __float_as_int(__ldg(vals + e)));
}

// ---------------------------------------------------------------------------
// Gather SpMM: warp per row, fp32 register accumulation (lane-contiguous),
// 2-edge unroll for MLP, bf16 hi/lo split output.
// ---------------------------------------------------------------------------
__global__ __launch_bounds__(256) void spmm_gather_kernel(
        const float* __restrict__ x) {
    const int wid = threadIdx.x >> 5;
    const int lane = threadIdx.x & 31;
    const int r = blockIdx.x * 8 + wid;

    const int cnt = g_row_cnt[r];
    const int start = g_loc[r] + g_blk_off[r >> 10] - cnt;
    const int2* ep = g_csr_pack + start;

    float a[8];
#pragma unroll
    for (int q = 0; q < 8; ++q) a[q] = 0.f;

    int j = 0;
    for (; j + 2 <= cnt; j += 2) {
        int2 e0 = __ldg(ep + j);
        int2 e1 = __ldg(ep + j + 1);
        float v0 = __int_as_float(e0.y);
        float v1 = __int_as_float(e1.y);
        const float4* xs0 = (const float4*)(x + (size_t)e0.x * D) + 2 * lane;
        const float4* xs1 = (const float4*)(x + (size_t)e1.x * D) + 2 * lane;
        float4 p0 = __ldg(xs0), p1 = __ldg(xs0 + 1);
        float4 q0 = __ldg(xs1), q1 = __ldg(xs1 + 1);
        a[0] += v0 * p0.x; a[1] += v0 * p0.y; a[2] += v0 * p0.z; a[3] += v0 * p0.w;
        a[4] += v0 * p1.x; a[5] += v0 * p1.y; a[6] += v0 * p1.z; a[7] += v0 * p1.w;
        a[0] += v1 * q0.x; a[1] += v1 * q0.y; a[2] += v1 * q0.z; a[3] += v1 * q0.w;
        a[4] += v1 * q1.x; a[5] += v1 * q1.y; a[6] += v1 * q1.z; a[7] += v1 * q1.w;
    }
    if (j < cnt) {
        int2 e0 = __ldg(ep + j);
        float v0 = __int_as_float(e0.y);
        const float4* xs0 = (const float4*)(x + (size_t)e0.x * D) + 2 * lane;
        float4 p0 = __ldg(xs0), p1 = __ldg(xs0 + 1);
        a[0] += v0 * p0.x; a[1] += v0 * p0.y; a[2] += v0 * p0.z; a[3] += v0 * p0.w;
        a[4] += v0 * p1.x; a[5] += v0 * p1.y; a[6] += v0 * p1.z; a[7] += v0 * p1.w;
    }

    uint32_t h[4], l[4];
    split2(a[0], a[1], h[0], l[0]);
    split2(a[2], a[3], h[1], l[1]);
    split2(a[4], a[5], h[2], l[2]);
    split2(a[6], a[7], h[3], l[3]);
    size_t o = (size_t)r * D + lane * 8;
    *(uint4*)(g_mapped_hi + o) = make_uint4(h[0], h[1], h[2], h[3]);
    *(uint4*)(g_mapped_lo + o) = make_uint4(l[0], l[1], l[2], l[3]);
}

// ---------------------------------------------------------------------------
// W transpose + bf16 split (32x32 tiles)
// ---------------------------------------------------------------------------
__global__ __launch_bounds__(256) void wconv_kernel(const float* __restrict__ W) {
    __shared__ float t[32][33];
    const int tid = threadIdx.x;
    const int k0 = (blockIdx.x >> 3) * 32;
    const int n0 = (blockIdx.x & 7) * 32;
    {
        int row = tid >> 3, c4 = tid & 7;
        float4 v = __ldg((const float4*)(W + (size_t)(k0 + row) * D + n0 + c4 * 4));
        t[row][c4 * 4 + 0] = v.x;
        t[row][c4 * 4 + 1] = v.y;
        t[row][c4 * 4 + 2] = v.z;
        t[row][c4 * 4 + 3] = v.w;
    }
    __syncthreads();
    {
        int nl = tid >> 3, kq = (tid & 7) * 4;
        uint16_t h[4], l[4];
#pragma unroll
        for (int i = 0; i < 4; ++i) {
            float v = t[kq + i][nl];
            __nv_bfloat16 hb = __float2bfloat16(v);
            __nv_bfloat16 lb = __float2bfloat16(v - __bfloat162float(hb));
            h[i] = *(uint16_t*)&hb;
            l[i] = *(uint16_t*)&lb;
        }
        size_t o = (size_t)(n0 + nl) * D + k0 + kq;
        *(uint2*)(g_wt_hi + o) = *(uint2*)h;
        *(uint2*)(g_wt_lo + o) = *(uint2*)l;
    }
}

// ---------------------------------------------------------------------------
// GEMM + bias + LayerNorm + GELU, cp.async double-buffered staging.
// ---------------------------------------------------------------------------
extern __shared__ char dynsmem[];

__device__ __forceinline__ void issue_chunk(uint32_t sb, int buf, int row0,
                                            int kc, int tid) {
    uint32_t b = sb + buf * BUF_STRIDE;
    {   // A: 64 rows x 32 k, hi+lo
        int row = tid >> 2, seg = tid & 3;
        size_t gs = (size_t)(row0 + row) * D + kc * KC + seg * 8;
        uint32_t off = (uint32_t)(row * 80 + seg * 16);
        cpasync16(b + OFF_AHI + off, g_mapped_hi + gs);
        cpasync16(b + OFF_ALO + off, g_mapped_lo + gs);
    }
#pragma unroll
    for (int i = 0; i < 4; ++i) {   // B: 256 n x 32 k, hi+lo
        int task = i * 256 + tid;
        int n = task >> 2, seg = task & 3;
        size_t gs = (size_t)n * D + kc * KC + seg * 8;
        uint32_t off = (uint32_t)(n * 80 + seg * 16);
        cpasync16(b + OFF_BHI + off, g_wt_hi + gs);
        cpasync16(b + OFF_BLO + off, g_wt_lo + gs);
    }
    asm volatile("cp.async.commit_group;" ::: "memory");
}

__global__ __launch_bounds__(256, 2) void gemm_ln_gelu_kernel(
        const float* __restrict__ bias,
        const float* __restrict__ gamma,
        const float* __restrict__ beta,
        float* __restrict__ out) {
    char* sm = dynsmem;
    const uint32_t sb = smem_u32(sm);
    const int tid = threadIdx.x;
    const int wid = tid >> 5;
    const int lane = tid & 31;
    const int gr = lane >> 2;
    const int tc = lane & 3;
    const int warp_m = wid & 1;
    const int warp_n = wid >> 1;
    const int row0 = blockIdx.x * BM;

    {
        ((float*)(sm + SOFF_BIAS))[tid]  = bias[tid];
        ((float*)(sm + SOFF_GAMMA))[tid] = gamma[tid];
        ((float*)(sm + SOFF_BETA))[tid]  = beta[tid];
    }

    float acc[2][8][4];
#pragma unroll
    for (int mt = 0; mt < 2; ++mt)
#pragma unroll
        for (int nt = 0; nt < 8; ++nt)
#pragma unroll
            for (int q = 0; q < 4; ++q) acc[mt][nt][q] = 0.f;

    issue_chunk(sb, 0, row0, 0, tid);

#pragma unroll 1
    for (int kc = 0; kc < NCHUNK; ++kc) {
        if (kc + 1 < NCHUNK) issue_chunk(sb, (kc + 1) & 1, row0, kc + 1, tid);
        if (kc + 1 < NCHUNK)
            asm volatile("cp.async.wait_group 1;" ::: "memory");
        else
            asm volatile("cp.async.wait_group 0;" ::: "memory");
        __syncthreads();

        const char* buf = sm + (kc & 1) * BUF_STRIDE;
        const uint16_t* pAhi = (const uint16_t*)(buf + OFF_AHI);
        const uint16_t* pAlo = (const uint16_t*)(buf + OFF_ALO);
        const uint16_t* pBhi = (const uint16_t*)(buf + OFF_BHI);
        const uint16_t* pBlo = (const uint16_t*)(buf + OFF_BLO);

#pragma unroll
        for (int ks = 0; ks < 2; ++ks) {
            uint32_t ahi[2][4], alo[2][4];
#pragma unroll
            for (int mt = 0; mt < 2; ++mt) {
                int ar = warp_m * 32 + mt * 16 + gr;
                int ak = ks * 16 + tc * 2;
                const uint16_t* ph = pAhi + ar * 40 + ak;
                const uint16_t* pl = pAlo + ar * 40 + ak;
                ahi[mt][0] = *(const uint32_t*)(ph);
                ahi[mt][1] = *(const uint32_t*)(ph + 320);
                ahi[mt][2] = *(const uint32_t*)(ph + 8);
                ahi[mt][3] = *(const uint32_t*)(ph + 328);
                alo[mt][0] = *(const uint32_t*)(pl);
                alo[mt][1] = *(const uint32_t*)(pl + 320);
                alo[mt][2] = *(const uint32_t*)(pl + 8);
                alo[mt][3] = *(const uint32_t*)(pl + 328);
            }
#pragma unroll
            for (int nt = 0; nt < 8; ++nt) {
                int bn = warp_n * 64 + nt * 8 + gr;
                int bk = ks * 16 + tc * 2;
                uint32_t bh0 = *(const uint32_t*)(pBhi + bn * 40 + bk);
                uint32_t bh1 = *(const uint32_t*)(pBhi + bn * 40 + bk + 8);
                uint32_t bl0 = *(const uint32_t*)(pBlo + bn * 40 + bk);
                uint32_t bl1 = *(const uint32_t*)(pBlo + bn * 40 + bk + 8);
#pragma unroll
                for (int mt = 0; mt < 2; ++mt) {
                    mma_bf16(acc[mt][nt], ahi[mt], bh0, bh1);
                    mma_bf16(acc[mt][nt], ahi[mt], bl0, bl1);
                    mma_bf16(acc[mt][nt], alo[mt], bh0, bh1);
                }
            }
        }
        __syncthreads();
    }

    // --- stage h = acc + bias into smem (buffers now free) ---
    {
        float* sH = (float*)(sm + SOFF_H);
        const float* sB = (const float*)(sm + SOFF_BIAS);
#pragma unroll
        for (int mt = 0; mt < 2; ++mt) {
#pragma unroll
            for (int nt = 0; nt < 8; ++nt) {
                int r = warp_m * 32 + mt * 16 + gr;
                int c = warp_n * 64 + nt * 8 + tc * 2;
                float b0 = sB[c], b1 = sB[c + 1];
                float* p0 = &sH[r * H_STRIDE + c];
                p0[0] = acc[mt][nt][0] + b0;
                p0[1] = acc[mt][nt][1] + b1;
                float* p1 = &sH[(r + 8) * H_STRIDE + c];
                p1[0] = acc[mt][nt][2] + b0;
                p1[1] = acc[mt][nt][3] + b1;
            }
        }
    }
    __syncthreads();

    // --- LayerNorm + exact GELU ---
    {
        const float* sH = (const float*)(sm + SOFF_H);
        const float* sG = (const float*)(sm + SOFF_GAMMA);
        const float* sBe = (const float*)(sm + SOFF_BETA);
#pragma unroll
        for (int rr = 0; rr < 8; ++rr) {
            const int r = wid * 8 + rr;
            float v[8];
            float s = 0.f;
#pragma unroll
            for (int j = 0; j < 8; ++j) {
                v[j] = sH[r * H_STRIDE + lane + j * 32];
                s += v[j];
            }
#pragma unroll
            for (int o = 16; o; o >>= 1) s += __shfl_xor_sync(0xffffffffu, s, o);
            const float mu = s * (1.f / 256.f);
            float q = 0.f;
#pragma unroll
            for (int j = 0; j < 8; ++j) {
                float d = v[j] - mu;
                q += d * d;
            }
#pragma unroll
            for (int o = 16; o; o >>= 1) q += __shfl_xor_sync(0xffffffffu, q, o);
            const float rstd = rsqrtf(q * (1.f / 256.f) + 1e-5f);

            float* orow = out + (size_t)(row0 + r) * D;
#pragma unroll
            for (int j = 0; j < 8; ++j) {
                const int c = lane + j * 32;
                float t = (v[j] - mu) * rstd * sG[c] + sBe[c];
                orow[c] = 0.5f * t * (1.f + erff(t * 0.70710678118654752f));
            }
        }
    }
}

// ---------------------------------------------------------------------------
// Launch
// ---------------------------------------------------------------------------
extern "C" void kernel_launch(void* const* d_in, const int* in_sizes, int n_in,
                              void* d_out, int out_size) {
    const float* x     = (const float*)d_in[0];
    const int*   rows  = (const int*)d_in[1];
    const int*   cols  = (const int*)d_in[2];
    const float* vals  = (const float*)d_in[3];
    const float* W     = (const float*)d_in[4];
    const float* bias  = (const float*)d_in[5];
    const float* gamma = (const float*)d_in[6];
    const float* beta  = (const float*)d_in[7];

    const int nnz = in_sizes[1];
    const int eblk = (nnz + 255) / 256;

    void* cnt_ptr = nullptr;
    cudaGetSymbolAddress(&cnt_ptr, g_row_cnt);
    cudaMemsetAsync(cnt_ptr, 0, N_TGT_PAD * sizeof(int));

    hist_kernel<<<eblk, 256>>>(rows, nnz);
    scanA_kernel<<<40, 256>>>();
    scanB_kernel<<<1, 32>>>();
    bucket_kernel<<<eblk, 256>>>(rows, cols, vals, nnz);

    spmm_gather_kernel<<<N_TGT / 8, 256>>>(x);
    wconv_kernel<<<64, 256>>>(W);

    cudaFuncSetAttribute(gemm_ln_gelu_kernel,
                         cudaFuncAttributeMaxDynamicSharedMemorySize,
                         SMEM_TOTAL);
    gemm_ln_gelu_kernel<<<NBLK, 256, SMEM_TOTAL>>>(
        bias, gamma, beta, (float*)d_out);
}

// round 12
// speedup vs baseline: 1.5525x; 1.4997x over previous
#include <cuda_runtime.h>
#include <cuda_fp16.h>
#include <math.h>
#include <stdint.h>

#define D 256
#define N_TGT 40000
#define NNZ_MAX 300000
#define N_TGT_PAD 40960
#define BM 64
#define NTILE (N_TGT / BM)       // 625
#define GRID 148                  // persistent: 1 CTA per SM

// ---------------- device scratch ----------------
__device__ __half g_mapped_h[(size_t)N_TGT * D];   // SpMM result, fp16
__device__ __half g_wt_h[D * D];                   // W^T [n][k], fp16
__device__ int   g_row_cnt[N_TGT_PAD];
__device__ int   g_loc[N_TGT_PAD];
__device__ int   g_blk[40];
__device__ int   g_blk_off[40];
__device__ int2  g_csr_pack[NNZ_MAX];

// ---------------- GEMM smem layout (bytes) ----------------
// A rows / B rows padded to 264 fp16 (528 B) -> (4*row + tc) banks, conflict-free
#define A_STRIDE 264
#define A_TILE_B (64 * 528)           // 33792
#define OFF_A0 0
#define OFF_A1 33792
#define OFF_B  67584                   // 256 x 528 = 135168
#define OFF_BIAS  202752               // 256 floats
#define OFF_GAMMA 203776
#define OFF_BETA  204800
#define OFF_PART  205824               // 64 x 4 float2 = 2048
#define OFF_STAT  207872               // 64 float2 = 512
#define SMEM_TOTAL 208384

__device__ __forceinline__ uint32_t smem_u32(const void* p) {
    uint32_t a;
    asm("{ .reg .u64 t; cvta.to.shared.u64 t, %1; cvt.u32.u64 %0, t; }"
        : "=r"(a) : "l"(p));
    return a;
}

__device__ __forceinline__ void cpasync16(uint32_t dst, const void* src) {
    asm volatile("cp.async.ca.shared.global [%0], [%1], 16;"
                 :: "r"(dst), "l"(src) : "memory");
}

__device__ __forceinline__ void mma_fp16(float* c, const uint32_t* a,
                                         uint32_t b0, uint32_t b1) {
    asm volatile(
        "mma.sync.aligned.m16n8k16.row.col.f32.f16.f16.f32 "
        "{%0,%1,%2,%3}, {%4,%5,%6,%7}, {%8,%9}, {%0,%1,%2,%3};"
        : "+f"(c[0]), "+f"(c[1]), "+f"(c[2]), "+f"(c[3])
        : "r"(a[0]), "r"(a[1]), "r"(a[2]), "r"(a[3]), "r"(b0), "r"(b1));
}

// ---------------------------------------------------------------------------
// CSR build (unchanged, proven)
// ---------------------------------------------------------------------------
__global__ void hist_kernel(const int* __restrict__ rows, int nnz) {
    int e = blockIdx.x * 256 + threadIdx.x;
    if (e < nnz) atomicAdd(&g_row_cnt[__ldg(rows + e)], 1);
}

__global__ __launch_bounds__(256) void scanA_kernel() {
    __shared__ int swarp[8];
    const int b = blockIdx.x, tid = threadIdx.x;
    const int lane = tid & 31, wid = tid >> 5;
    int4 v = ((const int4*)g_row_cnt)[b * 256 + tid];
    int tsum = v.x + v.y + v.z + v.w;
    int inc = tsum;
#pragma unroll
    for (int o = 1; o < 32; o <<= 1) {
        int n = __shfl_up_sync(0xffffffffu, inc, o);
        if (lane >= o) inc += n;
    }
    if (lane == 31) swarp[wid] = inc;
    __syncthreads();
    if (wid == 0 && lane < 8) {
        int s = swarp[lane];
        int si = s;
#pragma unroll
        for (int o = 1; o < 8; o <<= 1) {
            int n = __shfl_up_sync(0xffu, si, o);
            if (lane >= o) si += n;
        }
        swarp[lane] = si - s;
        if (lane == 7) g_blk[b] = si;
    }
    __syncthreads();
    int base = swarp[wid] + inc - tsum;
    int4 o4;
    o4.x = base;
    o4.y = base + v.x;
    o4.z = o4.y + v.y;
    o4.w = o4.z + v.z;
    ((int4*)g_loc)[b * 256 + tid] = o4;
}

__global__ void scanB_kernel() {
    int l = threadIdx.x;
    int s0 = (2 * l < 40) ? g_blk[2 * l] : 0;
    int s1 = (2 * l + 1 < 40) ? g_blk[2 * l + 1] : 0;
    int p = s0 + s1, inc = p;
#pragma unroll
    for (int o = 1; o < 32; o <<= 1) {
        int n = __shfl_up_sync(0xffffffffu, inc, o);
        if (l >= o) inc += n;
    }
    int excl = inc - p;
    if (2 * l < 40) g_blk_off[2 * l] = excl;
    if (2 * l + 1 < 40) g_blk_off[2 * l + 1] = excl + s0;
}

__global__ void bucket_kernel(const int* __restrict__ rows,
                              const int* __restrict__ cols,
                              const float* __restrict__ vals, int nnz) {
    int e = blockIdx.x * 256 + threadIdx.x;
    if (e >= nnz) return;
    int r = __ldg(rows + e);
    int lp = atomicAdd(&g_loc[r], 1);
    int pos = lp + g_blk_off[r >> 10];
    g_csr_pack[pos] = make_int2(__ldg(cols + e),
                                __float_as_int(__ldg(vals + e)));
}

// ---------------------------------------------------------------------------
// Gather SpMM: warp per row, fp32 accumulation, fp16 output.
// ---------------------------------------------------------------------------
__global__ __launch_bounds__(256) void spmm_gather_kernel(
        const float* __restrict__ x) {
    const int wid = threadIdx.x >> 5;
    const int lane = threadIdx.x & 31;
    const int r = blockIdx.x * 8 + wid;

    const int cnt = g_row_cnt[r];
    const int start = g_loc[r] + g_blk_off[r >> 10] - cnt;
    const int2* ep = g_csr_pack + start;

    float a[8];
#pragma unroll
    for (int q = 0; q < 8; ++q) a[q] = 0.f;

    int j = 0;
    for (; j + 2 <= cnt; j += 2) {
        int2 e0 = __ldg(ep + j);
        int2 e1 = __ldg(ep + j + 1);
        float v0 = __int_as_float(e0.y);
        float v1 = __int_as_float(e1.y);
        const float4* xs0 = (const float4*)(x + (size_t)e0.x * D) + 2 * lane;
        const float4* xs1 = (const float4*)(x + (size_t)e1.x * D) + 2 * lane;
        float4 p0 = __ldg(xs0), p1 = __ldg(xs0 + 1);
        float4 q0 = __ldg(xs1), q1 = __ldg(xs1 + 1);
        a[0] += v0 * p0.x; a[1] += v0 * p0.y; a[2] += v0 * p0.z; a[3] += v0 * p0.w;
        a[4] += v0 * p1.x; a[5] += v0 * p1.y; a[6] += v0 * p1.z; a[7] += v0 * p1.w;
        a[0] += v1 * q0.x; a[1] += v1 * q0.y; a[2] += v1 * q0.z; a[3] += v1 * q0.w;
        a[4] += v1 * q1.x; a[5] += v1 * q1.y; a[6] += v1 * q1.z; a[7] += v1 * q1.w;
    }
    if (j < cnt) {
        int2 e0 = __ldg(ep + j);
        float v0 = __int_as_float(e0.y);
        const float4* xs0 = (const float4*)(x + (size_t)e0.x * D) + 2 * lane;
        float4 p0 = __ldg(xs0), p1 = __ldg(xs0 + 1);
        a[0] += v0 * p0.x; a[1] += v0 * p0.y; a[2] += v0 * p0.z; a[3] += v0 * p0.w;
        a[4] += v0 * p1.x; a[5] += v0 * p1.y; a[6] += v0 * p1.z; a[7] += v0 * p1.w;
    }

    __half2 h0 = __floats2half2_rn(a[0], a[1]);
    __half2 h1 = __floats2half2_rn(a[2], a[3]);
    __half2 h2 = __floats2half2_rn(a[4], a[5]);
    __half2 h3 = __floats2half2_rn(a[6], a[7]);
    uint4 pack = make_uint4(*(uint32_t*)&h0, *(uint32_t*)&h1,
                            *(uint32_t*)&h2, *(uint32_t*)&h3);
    *(uint4*)(g_mapped_h + (size_t)r * D + lane * 8) = pack;
}

// ---------------------------------------------------------------------------
// W transpose -> fp16: 32x32 tiles.
// ---------------------------------------------------------------------------
__global__ __launch_bounds__(256) void wconv_kernel(const float* __restrict__ W) {
    __shared__ float t[32][33];
    const int tid = threadIdx.x;
    const int k0 = (blockIdx.x >> 3) * 32;
    const int n0 = (blockIdx.x & 7) * 32;
    {
        int row = tid >> 3, c4 = tid & 7;
        float4 v = __ldg((const float4*)(W + (size_t)(k0 + row) * D + n0 + c4 * 4));
        t[row][c4 * 4 + 0] = v.x;
        t[row][c4 * 4 + 1] = v.y;
        t[row][c4 * 4 + 2] = v.z;
        t[row][c4 * 4 + 3] = v.w;
    }
    __syncthreads();
    {
        int nl = tid >> 3, kq = (tid & 7) * 4;
        __half2 p0 = __floats2half2_rn(t[kq][nl], t[kq + 1][nl]);
        __half2 p1 = __floats2half2_rn(t[kq + 2][nl], t[kq + 3][nl]);
        uint2 pk = make_uint2(*(uint32_t*)&p0, *(uint32_t*)&p1);
        *(uint2*)(g_wt_h + (size_t)(n0 + nl) * D + k0 + kq) = pk;
    }
}

// ---------------------------------------------------------------------------
// Persistent GEMM: 148 CTAs, B=W (fp16) resident in smem, tiles of 64 rows
// streamed with one-tile-ahead A prefetch.  mapped@W + bias + LN + GELU.
// ---------------------------------------------------------------------------
extern __shared__ char dynsmem[];

__global__ __launch_bounds__(256, 1) void gemm_ln_gelu_kernel(
        const float* __restrict__ bias,
        const float* __restrict__ gamma,
        const float* __restrict__ beta,
        float* __restrict__ out) {
    char* sm = dynsmem;
    const uint32_t sb = smem_u32(sm);
    const int tid = threadIdx.x;
    const int wid = tid >> 5;
    const int lane = tid & 31;
    const int gr = lane >> 2;
    const int tc = lane & 3;
    const int warp_m = wid & 1;
    const int warp_n = wid >> 1;

    ((float*)(sm + OFF_BIAS))[tid]  = bias[tid];
    ((float*)(sm + OFF_GAMMA))[tid] = gamma[tid];
    ((float*)(sm + OFF_BETA))[tid]  = beta[tid];

    // --- load resident B = Wt fp16 [256][256] into padded smem (once) ---
#pragma unroll
    for (int i = 0; i < 32; ++i) {
        int task = i * 256 + tid;
        int n = task >> 5, seg = task & 31;
        cpasync16(sb + OFF_B + n * 528 + seg * 16, g_wt_h + n * 256 + seg * 8);
    }
    asm volatile("cp.async.commit_group;" ::: "memory");

    // --- prefetch first A tile ---
    {
        int t0 = blockIdx.x;
#pragma unroll
        for (int i = 0; i < 8; ++i) {
            int task = i * 256 + tid;
            int row = task >> 5, seg = task & 31;
            cpasync16(sb + OFF_A0 + row * 528 + seg * 16,
                      g_mapped_h + (size_t)(t0 * BM + row) * D + seg * 8);
        }
        asm volatile("cp.async.commit_group;" ::: "memory");
    }

    const float* sBias = (const float*)(sm + OFF_BIAS);
    const float* sG    = (const float*)(sm + OFF_GAMMA);
    const float* sBe   = (const float*)(sm + OFF_BETA);
    float2* sPart = (float2*)(sm + OFF_PART);
    float2* sStat = (float2*)(sm + OFF_STAT);

    int i = 0;
#pragma unroll 1
    for (int t = blockIdx.x; t < NTILE; t += GRID, ++i) {
        asm volatile("cp.async.wait_group 0;" ::: "memory");
        __syncthreads();

        // prefetch next tile into the other buffer
        if (t + GRID < NTILE) {
            uint32_t nb = sb + ((i + 1) & 1 ? OFF_A1 : OFF_A0);
#pragma unroll
            for (int p = 0; p < 8; ++p) {
                int task = p * 256 + tid;
                int row = task >> 5, seg = task & 31;
                cpasync16(nb + row * 528 + seg * 16,
                          g_mapped_h + (size_t)((t + GRID) * BM + row) * D + seg * 8);
            }
            asm volatile("cp.async.commit_group;" ::: "memory");
        }

        const uint16_t* pA = (const uint16_t*)(sm + ((i & 1) ? OFF_A1 : OFF_A0));
        const uint16_t* pB = (const uint16_t*)(sm + OFF_B);

        float acc[2][8][4];
#pragma unroll
        for (int mt = 0; mt < 2; ++mt)
#pragma unroll
            for (int nt = 0; nt < 8; ++nt)
#pragma unroll
                for (int q = 0; q < 4; ++q) acc[mt][nt][q] = 0.f;

#pragma unroll
        for (int ks = 0; ks < 16; ++ks) {
            uint32_t a[2][4];
#pragma unroll
            for (int mt = 0; mt < 2; ++mt) {
                const uint16_t* ph = pA + (warp_m * 32 + mt * 16 + gr) * A_STRIDE
                                        + ks * 16 + tc * 2;
                a[mt][0] = *(const uint32_t*)(ph);
                a[mt][1] = *(const uint32_t*)(ph + 8 * A_STRIDE);
                a[mt][2] = *(const uint32_t*)(ph + 8);
                a[mt][3] = *(const uint32_t*)(ph + 8 * A_STRIDE + 8);
            }
#pragma unroll
            for (int nt = 0; nt < 8; ++nt) {
                const uint16_t* pb = pB + (warp_n * 64 + nt * 8 + gr) * A_STRIDE
                                        + ks * 16 + tc * 2;
                uint32_t b0 = *(const uint32_t*)(pb);
                uint32_t b1 = *(const uint32_t*)(pb + 8);
                mma_fp16(acc[0][nt], a[0], b0, b1);
                mma_fp16(acc[1][nt], a[1], b0, b1);
            }
        }

        // ---- epilogue: bias, LN stats via quad-shuffle + smem, GELU, store ----
        float s[2][2], q[2][2];
#pragma unroll
        for (int mt = 0; mt < 2; ++mt)
#pragma unroll
            for (int h = 0; h < 2; ++h) { s[mt][h] = 0.f; q[mt][h] = 0.f; }

#pragma unroll
        for (int mt = 0; mt < 2; ++mt)
#pragma unroll
            for (int nt = 0; nt < 8; ++nt) {
                int c = warp_n * 64 + nt * 8 + tc * 2;
                float b0 = sBias[c], b1 = sBias[c + 1];
#pragma unroll
                for (int h = 0; h < 2; ++h) {
                    float v0 = acc[mt][nt][2 * h] + b0;
                    float v1 = acc[mt][nt][2 * h + 1] + b1;
                    acc[mt][nt][2 * h] = v0;
                    acc[mt][nt][2 * h + 1] = v1;
                    s[mt][h] += v0 + v1;
                    q[mt][h] += v0 * v0 + v1 * v1;
                }
            }
#pragma unroll
        for (int mt = 0; mt < 2; ++mt)
#pragma unroll
            for (int h = 0; h < 2; ++h) {
#pragma unroll
                for (int o = 1; o < 4; o <<= 1) {
                    s[mt][h] += __shfl_xor_sync(0xffffffffu, s[mt][h], o);
                    q[mt][h] += __shfl_xor_sync(0xffffffffu, q[mt][h], o);
                }
            }
        if (tc == 0) {
#pragma unroll
            for (int mt = 0; mt < 2; ++mt)
#pragma unroll
                for (int h = 0; h < 2; ++h) {
                    int r = warp_m * 32 + mt * 16 + 8 * h + gr;
                    sPart[r * 4 + warp_n] = make_float2(s[mt][h], q[mt][h]);
                }
        }
        __syncthreads();
        if (tid < 64) {
            float2 p0 = sPart[tid * 4 + 0];
            float2 p1 = sPart[tid * 4 + 1];
            float2 p2 = sPart[tid * 4 + 2];
            float2 p3 = sPart[tid * 4 + 3];
            float S = p0.x + p1.x + p2.x + p3.x;
            float Q = p0.y + p1.y + p2.y + p3.y;
            float mu = S * (1.f / 256.f);
            float var = Q * (1.f / 256.f) - mu * mu;
            sStat[tid] = make_float2(mu, rsqrtf(fmaxf(var, 0.f) + 1e-5f));
        }
        __syncthreads();

#pragma unroll
        for (int mt = 0; mt < 2; ++mt)
#pragma unroll
            for (int h = 0; h < 2; ++h) {
                int r = warp_m * 32 + mt * 16 + 8 * h + gr;
                float2 st = sStat[r];
                float* orow = out + (size_t)(t * BM + r) * D;
#pragma unroll
                for (int nt = 0; nt < 8; ++nt) {
                    int c = warp_n * 64 + nt * 8 + tc * 2;
                    float t0 = (acc[mt][nt][2 * h] - st.x) * st.y * sG[c] + sBe[c];
                    float t1 = (acc[mt][nt][2 * h + 1] - st.x) * st.y * sG[c + 1] + sBe[c + 1];
                    float2 g;
                    g.x = 0.5f * t0 * (1.f + erff(t0 * 0.70710678118654752f));
                    g.y = 0.5f * t1 * (1.f + erff(t1 * 0.70710678118654752f));
                    *(float2*)(orow + c) = g;
                }
            }
        // next-iteration top __syncthreads + wait protect sPart/sStat and A buf
    }
}

// ---------------------------------------------------------------------------
// Launch
// ---------------------------------------------------------------------------
extern "C" void kernel_launch(void* const* d_in, const int* in_sizes, int n_in,
                              void* d_out, int out_size) {
    const float* x     = (const float*)d_in[0];
    const int*   rows  = (const int*)d_in[1];
    const int*   cols  = (const int*)d_in[2];
    const float* vals  = (const float*)d_in[3];
    const float* W     = (const float*)d_in[4];
    const float* bias  = (const float*)d_in[5];
    const float* gamma = (const float*)d_in[6];
    const float* beta  = (const float*)d_in[7];

    const int nnz = in_sizes[1];
    const int eblk = (nnz + 255) / 256;

    void* cnt_ptr = nullptr;
    cudaGetSymbolAddress(&cnt_ptr, g_row_cnt);
    cudaMemsetAsync(cnt_ptr, 0, N_TGT_PAD * sizeof(int));

    hist_kernel<<<eblk, 256>>>(rows, nnz);
    scanA_kernel<<<40, 256>>>();
    scanB_kernel<<<1, 32>>>();
    bucket_kernel<<<eblk, 256>>>(rows, cols, vals, nnz);

    spmm_gather_kernel<<<N_TGT / 8, 256>>>(x);
    wconv_kernel<<<64, 256>>>(W);

    cudaFuncSetAttribute(gemm_ln_gelu_kernel,
                         cudaFuncAttributeMaxDynamicSharedMemorySize,
                         SMEM_TOTAL);
    gemm_ln_gelu_kernel<<<GRID, 256, SMEM_TOTAL>>>(
        bias, gamma, beta, (float*)d_out);
}